// round 8
// baseline (speedup 1.0000x reference)
#include <cuda_runtime.h>
#include <cuda_fp16.h>
#include <cstdint>

#define N_NODES 1000000
#define N_EDGES 5000000
#define N_LABEL 2000000
#define FDIM    16

#define SCAN_CHUNK 2048
#define NB ((N_NODES + SCAN_CHUNK - 1) / SCAN_CHUNK)   // 489

// Scratch (device globals — allocation is forbidden)
__device__ int      g_deg [N_NODES];
__device__ int      g_off [N_NODES + 1];
__device__ int      g_cur [N_NODES];
__device__ int      g_csr [N_EDGES];
__device__ int      g_scan_aux[1 + NB];    // [0]=ticket, [1..NB]=packed state
__device__ float    g_dinv[N_NODES];
__device__ unsigned g_msg1[N_NODES * 8];   // layer-1 messages, half2-packed
__device__ unsigned g_msg2[N_NODES * 8];   // layer-2 messages, half2-packed
__device__ float    g_pA  [N_NODES];       // dot(z_i, fc_w[0:16])
__device__ float    g_pB  [N_NODES];       // dot(z_i, fc_w[16:32])

// ---------------------------------------------------------------------------
// E % 4 == 0: int4-vectorized degree count
__global__ void k_count(const int4* __restrict__ dst4) {
    int e = blockIdx.x * blockDim.x + threadIdx.x;
    if (e < N_EDGES / 4) {
        int4 d = dst4[e];
        atomicAdd(&g_deg[d.x], 1);
        atomicAdd(&g_deg[d.y], 1);
        atomicAdd(&g_deg[d.z], 1);
        atomicAdd(&g_deg[d.w], 1);
    }
}

// dinv only needs deg — runs on the side stream, unblocks mm1 early.
__global__ void k_dinv() {
    int i = blockIdx.x * blockDim.x + threadIdx.x;
    if (i < N_NODES) g_dinv[i] = rsqrtf((float)(g_deg[i] + 1));  // +1 self loop
}

// ---------------------------------------------------------------------------
// Single-pass exclusive scan (decoupled lookback, ticket-ordered blocks).
// State word: (sum << 2) | flag,  flag: 0=empty, 1=aggregate, 2=prefix.
// Writes g_off and g_cur. Total sum 5e6 < 2^23 so the pack is safe.
__global__ void k_scan() {
    __shared__ int sbid;
    __shared__ int s[256];
    __shared__ int spfx;
    int t = threadIdx.x;
    if (t == 0) sbid = atomicAdd(&g_scan_aux[0], 1);
    __syncthreads();
    int b = sbid;

    int base = b * SCAN_CHUNK + t * 8;
    int v[8], sum = 0;
    #pragma unroll
    for (int q = 0; q < 8; q++) {
        int idx = base + q;
        int d = (idx < N_NODES) ? g_deg[idx] : 0;
        v[q] = sum; sum += d;
    }
    s[t] = sum; __syncthreads();
    for (int o = 1; o < 256; o <<= 1) {
        int x = (t >= o) ? s[t - o] : 0;
        __syncthreads();
        s[t] += x;
        __syncthreads();
    }
    int agg = s[255];
    int excl = (t > 0) ? s[t - 1] : 0;

    volatile int* st = (volatile int*)(g_scan_aux + 1);
    if (t == 0) {
        if (b == 0) {
            st[0] = (agg << 2) | 2;            // prefix known immediately
            spfx = 0;
        } else {
            st[b] = (agg << 2) | 1;            // publish aggregate
            int prefix = 0;
            int p = b - 1;
            while (true) {
                int w = st[p];
                int f = w & 3;
                if (f == 0) continue;          // spin: predecessor not ready
                prefix += (w >> 2);
                if (f == 2) break;
                p--;
            }
            st[b] = ((prefix + agg) << 2) | 2; // publish inclusive prefix
            spfx = prefix;
        }
    }
    __syncthreads();
    int prefix = spfx;

    #pragma unroll
    for (int q = 0; q < 8; q++) {
        int idx = base + q;
        if (idx < N_NODES) {
            int o = v[q] + excl + prefix;
            g_off[idx] = o;
            g_cur[idx] = o;
        }
    }
    if (b == NB - 1 && t == 0) g_off[N_NODES] = N_EDGES;
}

// int4-vectorized CSR fill
__global__ void k_fill(const int4* __restrict__ src4, const int4* __restrict__ dst4) {
    int e = blockIdx.x * blockDim.x + threadIdx.x;
    if (e >= N_EDGES / 4) return;
    int4 s = src4[e];
    int4 d = dst4[e];
    g_csr[atomicAdd(&g_cur[d.x], 1)] = s.x;
    g_csr[atomicAdd(&g_cur[d.y], 1)] = s.y;
    g_csr[atomicAdd(&g_cur[d.z], 1)] = s.z;
    g_csr[atomicAdd(&g_cur[d.w], 1)] = s.w;
}

// ---------------------------------------------------------------------------
// K-mm1: msg1[i] = (embed[x[i]] @ W1) * dinv[i]  (half2-packed, 32 B/node)
__global__ void k_mm1(const int* __restrict__ x,
                      const float* __restrict__ embed,
                      const float* __restrict__ W1) {
    __shared__ float Ws[FDIM][FDIM];
    if (threadIdx.x < 256) {
        int k = threadIdx.x >> 4, j = threadIdx.x & 15;
        Ws[k][j] = W1[threadIdx.x];
    }
    __syncthreads();

    int i = blockIdx.x * blockDim.x + threadIdx.x;
    if (i >= N_NODES) return;

    const float4* rp = (const float4*)(embed + (size_t)x[i] * FDIM);
    float4 r0 = rp[0], r1 = rp[1], r2 = rp[2], r3 = rp[3];
    float row[FDIM] = {r0.x,r0.y,r0.z,r0.w, r1.x,r1.y,r1.z,r1.w,
                       r2.x,r2.y,r2.z,r2.w, r3.x,r3.y,r3.z,r3.w};
    float dv = g_dinv[i];
    float out[FDIM];
    #pragma unroll
    for (int j = 0; j < FDIM; j++) {
        float acc = 0.f;
        #pragma unroll
        for (int k = 0; k < FDIM; k++) acc = fmaf(row[k], Ws[k][j], acc);
        out[j] = acc * dv;
    }
    __half2 h[8];
    #pragma unroll
    for (int q = 0; q < 8; q++) h[q] = __floats2half2_rn(out[2*q], out[2*q+1]);
    uint4* mp = (uint4*)(g_msg1 + (size_t)i * 8);
    mp[0] = make_uint4(*(unsigned*)&h[0], *(unsigned*)&h[1], *(unsigned*)&h[2], *(unsigned*)&h[3]);
    mp[1] = make_uint4(*(unsigned*)&h[4], *(unsigned*)&h[5], *(unsigned*)&h[6], *(unsigned*)&h[7]);
}

// ---------------------------------------------------------------------------
__device__ __forceinline__ void acc_h4(float4& a, uint2 m) {
    float2 f0 = __half22float2(*(__half2*)&m.x);
    float2 f1 = __half22float2(*(__half2*)&m.y);
    a.x += f0.x; a.y += f0.y; a.z += f1.x; a.w += f1.y;
}

// Gather core (R6 form): 4 threads/node, uint2 loads, batches of 4 with
// clamped indices + predicated accumulate — no serial remainder chain.
__device__ __forceinline__ float4 gather_acc(const uint2* __restrict__ M,
                                             int node, int t, int o0, int o1) {
    float4 acc = make_float4(0.f, 0.f, 0.f, 0.f);
    acc_h4(acc, M[(size_t)node * 4 + t]);          // self message

    int last = o1 - 1;
    for (int j = o0; j < o1; j += 4) {
        int j1 = min(j + 1, last), j2 = min(j + 2, last), j3 = min(j + 3, last);
        int s0 = g_csr[j],  s1 = g_csr[j1];
        int s2 = g_csr[j2], s3 = g_csr[j3];
        uint2 m0 = M[(size_t)s0 * 4 + t];
        uint2 m1 = M[(size_t)s1 * 4 + t];
        uint2 m2 = M[(size_t)s2 * 4 + t];
        uint2 m3 = M[(size_t)s3 * 4 + t];
        acc_h4(acc, m0);
        if (j + 1 < o1) acc_h4(acc, m1);
        if (j + 2 < o1) acc_h4(acc, m2);
        if (j + 3 < o1) acc_h4(acc, m3);
    }
    return acc;
}

// K-gather1 fused with layer-2 matmul. Grid exact: 1e6/64 blocks — full warps.
__global__ void k_gather_mm2(const float* __restrict__ W2,
                             const float* __restrict__ b1) {
    __shared__ float Ws[FDIM][FDIM];
    __shared__ float bs[FDIM];
    if (threadIdx.x < 256) {
        int k = threadIdx.x >> 4, j = threadIdx.x & 15;
        Ws[k][j] = W2[threadIdx.x];
        if (threadIdx.x < FDIM) bs[threadIdx.x] = b1[threadIdx.x];
    }
    __syncthreads();

    int node  = blockIdx.x * 64 + (threadIdx.x >> 2);
    int t     = threadIdx.x & 3;
    int gbase = (threadIdx.x & 31) & ~3;

    float4 acc = gather_acc((const uint2*)g_msg1, node, t,
                            g_off[node], g_off[node + 1]);

    float dv = g_dinv[node];
    float h[4];
    h[0] = fmaxf(fmaf(dv, acc.x, bs[4*t + 0]), 0.f);
    h[1] = fmaxf(fmaf(dv, acc.y, bs[4*t + 1]), 0.f);
    h[2] = fmaxf(fmaf(dv, acc.z, bs[4*t + 2]), 0.f);
    h[3] = fmaxf(fmaf(dv, acc.w, bs[4*t + 3]), 0.f);

    float o[4] = {0.f, 0.f, 0.f, 0.f};
    #pragma unroll
    for (int k = 0; k < FDIM; k++) {
        float hk = __shfl_sync(0xFFFFFFFFu, h[k & 3], gbase + (k >> 2));
        o[0] = fmaf(hk, Ws[k][4*t + 0], o[0]);
        o[1] = fmaf(hk, Ws[k][4*t + 1], o[1]);
        o[2] = fmaf(hk, Ws[k][4*t + 2], o[2]);
        o[3] = fmaf(hk, Ws[k][4*t + 3], o[3]);
    }
    __half2 p0 = __floats2half2_rn(o[0] * dv, o[1] * dv);
    __half2 p1 = __floats2half2_rn(o[2] * dv, o[3] * dv);
    ((uint2*)g_msg2)[(size_t)node * 4 + t] =
        make_uint2(*(unsigned*)&p0, *(unsigned*)&p1);
}

// K-gather2 fused with final FC partials:
//   z = dinv*(msg2[i] + Σ msg2[s]) + b2
//   pA[i] = dot(z, fc_w[0:16]);  pB[i] = dot(z, fc_w[16:32])
__global__ void k_gather_z(const float* __restrict__ b2,
                           const float* __restrict__ fc_w) {
    __shared__ float bs[FDIM];
    __shared__ float fw[32];
    if (threadIdx.x < FDIM) bs[threadIdx.x] = b2[threadIdx.x];
    if (threadIdx.x < 32)   fw[threadIdx.x] = fc_w[threadIdx.x];
    __syncthreads();

    int node = blockIdx.x * 64 + (threadIdx.x >> 2);
    int t    = threadIdx.x & 3;

    float4 acc = gather_acc((const uint2*)g_msg2, node, t,
                            g_off[node], g_off[node + 1]);

    float dv = g_dinv[node];
    float z0 = fmaf(dv, acc.x, bs[4*t + 0]);
    float z1 = fmaf(dv, acc.y, bs[4*t + 1]);
    float z2 = fmaf(dv, acc.z, bs[4*t + 2]);
    float z3 = fmaf(dv, acc.w, bs[4*t + 3]);

    float pa = z0 * fw[4*t] + z1 * fw[4*t+1] + z2 * fw[4*t+2] + z3 * fw[4*t+3];
    float pb = z0 * fw[16+4*t] + z1 * fw[16+4*t+1]
             + z2 * fw[16+4*t+2] + z3 * fw[16+4*t+3];

    pa += __shfl_xor_sync(0xFFFFFFFFu, pa, 1);
    pa += __shfl_xor_sync(0xFFFFFFFFu, pa, 2);
    pb += __shfl_xor_sync(0xFFFFFFFFu, pb, 1);
    pb += __shfl_xor_sync(0xFFFFFFFFu, pb, 2);

    if (t == 0) {
        g_pA[node] = pa;
        g_pB[node] = pb;
    }
}

// ---------------------------------------------------------------------------
// K-predict, 2 edges/thread: out[e] = pA[la[e]] + pB[lb[e]] + fc_b
__global__ void k_predict(const int* __restrict__ la,
                          const int* __restrict__ lb,
                          const float* __restrict__ fc_b,
                          float* __restrict__ out) {
    int e = (blockIdx.x * blockDim.x + threadIdx.x) * 2;
    if (e >= N_LABEL) return;
    float fb = __ldg(fc_b);
    int a0 = la[e],     b0 = lb[e];
    int a1 = la[e + 1], b1 = lb[e + 1];   // N_LABEL even
    float r0 = g_pA[a0] + g_pB[b0] + fb;
    float r1 = g_pA[a1] + g_pB[b1] + fb;
    *(float2*)(out + e) = make_float2(r0, r1);
}

// ---------------------------------------------------------------------------
extern "C" void kernel_launch(void* const* d_in, const int* in_sizes, int n_in,
                              void* d_out, int out_size) {
    const int*   x     = (const int*)  d_in[0];
    const int*   ei    = (const int*)  d_in[1];
    const int*   eli   = (const int*)  d_in[2];
    const float* embed = (const float*)d_in[3];
    const float* W1    = (const float*)d_in[4];
    const float* b1    = (const float*)d_in[5];
    const float* W2    = (const float*)d_in[6];
    const float* b2    = (const float*)d_in[7];
    const float* fc_w  = (const float*)d_in[8];
    const float* fc_b  = (const float*)d_in[9];
    float*       out   = (float*)d_out;

    const int4* e_src4 = (const int4*)ei;
    const int4* e_dst4 = (const int4*)(ei + N_EDGES);
    const int*  l_a    = eli;
    const int*  l_b    = eli + N_LABEL;

    const int TB = 256;
    int gN  = (N_NODES + TB - 1) / TB;
    int gE4 = (N_EDGES / 4 + TB - 1) / TB;
    int gL2 = (N_LABEL / 2 + TB - 1) / TB;
    int gG  = N_NODES / 64;              // exact: 15625 blocks, 4 thr/node

    static cudaStream_t s2 = nullptr;
    static cudaEvent_t  e1 = nullptr, e2 = nullptr;
    static void* degPtr = nullptr;
    static void* auxPtr = nullptr;
    if (!e1) {
        if (cudaStreamCreateWithFlags(&s2, cudaStreamNonBlocking) != cudaSuccess) s2 = nullptr;
        cudaEventCreateWithFlags(&e1, cudaEventDisableTiming);
        cudaEventCreateWithFlags(&e2, cudaEventDisableTiming);
        cudaGetSymbolAddress(&degPtr, g_deg);
        cudaGetSymbolAddress(&auxPtr, g_scan_aux);
    }

    cudaMemsetAsync(degPtr, 0, N_NODES * sizeof(int), 0);
    cudaMemsetAsync(auxPtr, 0, (1 + NB) * sizeof(int), 0);
    k_count<<<gE4, TB>>>(e_dst4);

    if (s2) {
        cudaEventRecord(e1, 0);
        cudaStreamWaitEvent(s2, e1, 0);
        k_dinv<<<gN, TB, 0, s2>>>();
        k_mm1 <<<gN, TB, 0, s2>>>(x, embed, W1);
        cudaEventRecord(e2, s2);
        k_scan<<<NB, 256>>>();
        k_fill<<<gE4, TB>>>(e_src4, e_dst4);
        cudaStreamWaitEvent(0, e2, 0);
    } else {
        k_dinv<<<gN, TB>>>();
        k_scan<<<NB, 256>>>();
        k_fill<<<gE4, TB>>>(e_src4, e_dst4);
        k_mm1 <<<gN, TB>>>(x, embed, W1);
    }

    k_gather_mm2<<<gG, TB>>>(W2, b1);
    k_gather_z  <<<gG, TB>>>(b2, fc_w);
    k_predict   <<<gL2, TB>>>(l_a, l_b, fc_b, out);
}

// round 9
// speedup vs baseline: 1.0113x; 1.0113x over previous
#include <cuda_runtime.h>
#include <cuda_fp16.h>
#include <cstdint>

#define N_NODES 1000000
#define N_EDGES 5000000
#define N_LABEL 2000000
#define FDIM    16

#define SCAN_CHUNK 2048
#define NB ((N_NODES + SCAN_CHUNK - 1) / SCAN_CHUNK)   // 489

// Scratch (device globals — allocation is forbidden)
__device__ int      g_deg [N_NODES];
__device__ int      g_off [N_NODES + 1];
__device__ int      g_cur [N_NODES];
__device__ int      g_csr [N_EDGES];
__device__ int      g_bsum[NB];
__device__ float    g_dinv[N_NODES];
__device__ unsigned g_msg1[N_NODES * 8];   // layer-1 messages, half2-packed
__device__ unsigned g_msg2[N_NODES * 8];   // layer-2 messages, half2-packed
__device__ float    g_pA  [N_NODES];       // dot(z_i, fc_w[0:16])
__device__ float    g_pB  [N_NODES];       // dot(z_i, fc_w[16:32])

// ---------------------------------------------------------------------------
// 8 edges/thread degree count (E % 8 == 0): two int4 loads, high MLP
__global__ void k_count(const int4* __restrict__ dst4) {
    int e = blockIdx.x * blockDim.x + threadIdx.x;
    if (e < N_EDGES / 8) {
        int4 d0 = dst4[2*e], d1 = dst4[2*e + 1];
        atomicAdd(&g_deg[d0.x], 1);
        atomicAdd(&g_deg[d0.y], 1);
        atomicAdd(&g_deg[d0.z], 1);
        atomicAdd(&g_deg[d0.w], 1);
        atomicAdd(&g_deg[d1.x], 1);
        atomicAdd(&g_deg[d1.y], 1);
        atomicAdd(&g_deg[d1.z], 1);
        atomicAdd(&g_deg[d1.w], 1);
    }
}

// dinv only needs deg — runs on the side stream, unblocks mm1 early.
__global__ void k_dinv() {
    int i = blockIdx.x * blockDim.x + threadIdx.x;
    if (i < N_NODES) g_dinv[i] = rsqrtf((float)(g_deg[i] + 1));  // +1 self loop
}

// ---------------------------------------------------------------------------
// 3-phase exclusive scan of g_deg into g_off (shuffle-based block scans).
__global__ void k_scan1() {
    __shared__ int wsum[8];
    int b = blockIdx.x, t = threadIdx.x;
    int lane = t & 31, wid = t >> 5;

    int base = b * SCAN_CHUNK + t * 8;
    int v[8], sum = 0;
    #pragma unroll
    for (int q = 0; q < 8; q++) {
        int idx = base + q;
        int d = (idx < N_NODES) ? g_deg[idx] : 0;
        v[q] = sum; sum += d;
    }
    // warp inclusive scan of per-thread sums
    int x = sum;
    #pragma unroll
    for (int o = 1; o < 32; o <<= 1) {
        int y = __shfl_up_sync(0xFFFFFFFFu, x, o);
        if (lane >= o) x += y;
    }
    if (lane == 31) wsum[wid] = x;
    __syncthreads();
    if (t < 8) {
        int w = wsum[t];
        #pragma unroll
        for (int o = 1; o < 8; o <<= 1) {
            int y = __shfl_up_sync(0xFFu, w, o);
            if (t >= o) w += y;
        }
        wsum[t] = w;
    }
    __syncthreads();
    int excl = (x - sum) + (wid > 0 ? wsum[wid - 1] : 0);

    #pragma unroll
    for (int q = 0; q < 8; q++) {
        int idx = base + q;
        if (idx < N_NODES) g_off[idx] = v[q] + excl;
    }
    if (t == 255) g_bsum[b] = wsum[7];
}

__global__ void k_scan2() {   // one block, 512 threads (16 warps), NB=489 sums
    __shared__ int wsum[16];
    int t = threadIdx.x, lane = t & 31, wid = t >> 5;
    int d = (t < NB) ? g_bsum[t] : 0;
    int x = d;
    #pragma unroll
    for (int o = 1; o < 32; o <<= 1) {
        int y = __shfl_up_sync(0xFFFFFFFFu, x, o);
        if (lane >= o) x += y;
    }
    if (lane == 31) wsum[wid] = x;
    __syncthreads();
    if (t < 16) {
        int w = wsum[t];
        #pragma unroll
        for (int o = 1; o < 16; o <<= 1) {
            int y = __shfl_up_sync(0xFFFFu, w, o);
            if (t >= o) w += y;
        }
        wsum[t] = w;
    }
    __syncthreads();
    int incl = x + (wid > 0 ? wsum[wid - 1] : 0);
    if (t < NB) g_bsum[t] = incl - d;   // exclusive
}

__global__ void k_scan3() {
    int i = blockIdx.x * blockDim.x + threadIdx.x;
    if (i < N_NODES) {
        int o = g_off[i] + g_bsum[i >> 11];
        g_off[i] = o;
        g_cur[i] = o;
    }
    if (i == 0) g_off[N_NODES] = N_EDGES;
}

// 8 edges/thread CSR fill
__global__ void k_fill(const int4* __restrict__ src4, const int4* __restrict__ dst4) {
    int e = blockIdx.x * blockDim.x + threadIdx.x;
    if (e >= N_EDGES / 8) return;
    int4 s0 = src4[2*e], s1 = src4[2*e + 1];
    int4 d0 = dst4[2*e], d1 = dst4[2*e + 1];
    g_csr[atomicAdd(&g_cur[d0.x], 1)] = s0.x;
    g_csr[atomicAdd(&g_cur[d0.y], 1)] = s0.y;
    g_csr[atomicAdd(&g_cur[d0.z], 1)] = s0.z;
    g_csr[atomicAdd(&g_cur[d0.w], 1)] = s0.w;
    g_csr[atomicAdd(&g_cur[d1.x], 1)] = s1.x;
    g_csr[atomicAdd(&g_cur[d1.y], 1)] = s1.y;
    g_csr[atomicAdd(&g_cur[d1.z], 1)] = s1.z;
    g_csr[atomicAdd(&g_cur[d1.w], 1)] = s1.w;
}

// ---------------------------------------------------------------------------
// K-mm1: msg1[i] = (embed[x[i]] @ W1) * dinv[i]  (half2-packed, 32 B/node)
__global__ void k_mm1(const int* __restrict__ x,
                      const float* __restrict__ embed,
                      const float* __restrict__ W1) {
    __shared__ float Ws[FDIM][FDIM];
    if (threadIdx.x < 256) {
        int k = threadIdx.x >> 4, j = threadIdx.x & 15;
        Ws[k][j] = W1[threadIdx.x];
    }
    __syncthreads();

    int i = blockIdx.x * blockDim.x + threadIdx.x;
    if (i >= N_NODES) return;

    const float4* rp = (const float4*)(embed + (size_t)x[i] * FDIM);
    float4 r0 = rp[0], r1 = rp[1], r2 = rp[2], r3 = rp[3];
    float row[FDIM] = {r0.x,r0.y,r0.z,r0.w, r1.x,r1.y,r1.z,r1.w,
                       r2.x,r2.y,r2.z,r2.w, r3.x,r3.y,r3.z,r3.w};
    float dv = g_dinv[i];
    float out[FDIM];
    #pragma unroll
    for (int j = 0; j < FDIM; j++) {
        float acc = 0.f;
        #pragma unroll
        for (int k = 0; k < FDIM; k++) acc = fmaf(row[k], Ws[k][j], acc);
        out[j] = acc * dv;
    }
    __half2 h[8];
    #pragma unroll
    for (int q = 0; q < 8; q++) h[q] = __floats2half2_rn(out[2*q], out[2*q+1]);
    uint4* mp = (uint4*)(g_msg1 + (size_t)i * 8);
    mp[0] = make_uint4(*(unsigned*)&h[0], *(unsigned*)&h[1], *(unsigned*)&h[2], *(unsigned*)&h[3]);
    mp[1] = make_uint4(*(unsigned*)&h[4], *(unsigned*)&h[5], *(unsigned*)&h[6], *(unsigned*)&h[7]);
}

// ---------------------------------------------------------------------------
__device__ __forceinline__ void acc_h4(float4& a, uint2 m) {
    float2 f0 = __half22float2(*(__half2*)&m.x);
    float2 f1 = __half22float2(*(__half2*)&m.y);
    a.x += f0.x; a.y += f0.y; a.z += f1.x; a.w += f1.y;
}

// Gather core (R6 form): 4 threads/node, uint2 loads, batches of 4 with
// clamped indices + predicated accumulate — no serial remainder chain.
__device__ __forceinline__ float4 gather_acc(const uint2* __restrict__ M,
                                             int node, int t, int o0, int o1) {
    float4 acc = make_float4(0.f, 0.f, 0.f, 0.f);
    acc_h4(acc, M[(size_t)node * 4 + t]);          // self message

    int last = o1 - 1;
    for (int j = o0; j < o1; j += 4) {
        int j1 = min(j + 1, last), j2 = min(j + 2, last), j3 = min(j + 3, last);
        int s0 = g_csr[j],  s1 = g_csr[j1];
        int s2 = g_csr[j2], s3 = g_csr[j3];
        uint2 m0 = M[(size_t)s0 * 4 + t];
        uint2 m1 = M[(size_t)s1 * 4 + t];
        uint2 m2 = M[(size_t)s2 * 4 + t];
        uint2 m3 = M[(size_t)s3 * 4 + t];
        acc_h4(acc, m0);
        if (j + 1 < o1) acc_h4(acc, m1);
        if (j + 2 < o1) acc_h4(acc, m2);
        if (j + 3 < o1) acc_h4(acc, m3);
    }
    return acc;
}

// K-gather1 fused with layer-2 matmul. Grid exact: 1e6/64 blocks — full warps.
__global__ void k_gather_mm2(const float* __restrict__ W2,
                             const float* __restrict__ b1) {
    __shared__ float Ws[FDIM][FDIM];
    __shared__ float bs[FDIM];
    if (threadIdx.x < 256) {
        int k = threadIdx.x >> 4, j = threadIdx.x & 15;
        Ws[k][j] = W2[threadIdx.x];
        if (threadIdx.x < FDIM) bs[threadIdx.x] = b1[threadIdx.x];
    }
    __syncthreads();

    int node  = blockIdx.x * 64 + (threadIdx.x >> 2);
    int t     = threadIdx.x & 3;
    int gbase = (threadIdx.x & 31) & ~3;

    float4 acc = gather_acc((const uint2*)g_msg1, node, t,
                            g_off[node], g_off[node + 1]);

    float dv = g_dinv[node];
    float h[4];
    h[0] = fmaxf(fmaf(dv, acc.x, bs[4*t + 0]), 0.f);
    h[1] = fmaxf(fmaf(dv, acc.y, bs[4*t + 1]), 0.f);
    h[2] = fmaxf(fmaf(dv, acc.z, bs[4*t + 2]), 0.f);
    h[3] = fmaxf(fmaf(dv, acc.w, bs[4*t + 3]), 0.f);

    float o[4] = {0.f, 0.f, 0.f, 0.f};
    #pragma unroll
    for (int k = 0; k < FDIM; k++) {
        float hk = __shfl_sync(0xFFFFFFFFu, h[k & 3], gbase + (k >> 2));
        o[0] = fmaf(hk, Ws[k][4*t + 0], o[0]);
        o[1] = fmaf(hk, Ws[k][4*t + 1], o[1]);
        o[2] = fmaf(hk, Ws[k][4*t + 2], o[2]);
        o[3] = fmaf(hk, Ws[k][4*t + 3], o[3]);
    }
    __half2 p0 = __floats2half2_rn(o[0] * dv, o[1] * dv);
    __half2 p1 = __floats2half2_rn(o[2] * dv, o[3] * dv);
    ((uint2*)g_msg2)[(size_t)node * 4 + t] =
        make_uint2(*(unsigned*)&p0, *(unsigned*)&p1);
}

// K-gather2 fused with final FC partials:
//   z = dinv*(msg2[i] + Σ msg2[s]) + b2
//   pA[i] = dot(z, fc_w[0:16]);  pB[i] = dot(z, fc_w[16:32])
__global__ void k_gather_z(const float* __restrict__ b2,
                           const float* __restrict__ fc_w) {
    __shared__ float bs[FDIM];
    __shared__ float fw[32];
    if (threadIdx.x < FDIM) bs[threadIdx.x] = b2[threadIdx.x];
    if (threadIdx.x < 32)   fw[threadIdx.x] = fc_w[threadIdx.x];
    __syncthreads();

    int node = blockIdx.x * 64 + (threadIdx.x >> 2);
    int t    = threadIdx.x & 3;

    float4 acc = gather_acc((const uint2*)g_msg2, node, t,
                            g_off[node], g_off[node + 1]);

    float dv = g_dinv[node];
    float z0 = fmaf(dv, acc.x, bs[4*t + 0]);
    float z1 = fmaf(dv, acc.y, bs[4*t + 1]);
    float z2 = fmaf(dv, acc.z, bs[4*t + 2]);
    float z3 = fmaf(dv, acc.w, bs[4*t + 3]);

    float pa = z0 * fw[4*t] + z1 * fw[4*t+1] + z2 * fw[4*t+2] + z3 * fw[4*t+3];
    float pb = z0 * fw[16+4*t] + z1 * fw[16+4*t+1]
             + z2 * fw[16+4*t+2] + z3 * fw[16+4*t+3];

    pa += __shfl_xor_sync(0xFFFFFFFFu, pa, 1);
    pa += __shfl_xor_sync(0xFFFFFFFFu, pa, 2);
    pb += __shfl_xor_sync(0xFFFFFFFFu, pb, 1);
    pb += __shfl_xor_sync(0xFFFFFFFFu, pb, 2);

    if (t == 0) {
        g_pA[node] = pa;
        g_pB[node] = pb;
    }
}

// ---------------------------------------------------------------------------
// K-predict, 2 edges/thread: out[e] = pA[la[e]] + pB[lb[e]] + fc_b
__global__ void k_predict(const int* __restrict__ la,
                          const int* __restrict__ lb,
                          const float* __restrict__ fc_b,
                          float* __restrict__ out) {
    int e = (blockIdx.x * blockDim.x + threadIdx.x) * 2;
    if (e >= N_LABEL) return;
    float fb = __ldg(fc_b);
    int a0 = la[e],     b0 = lb[e];
    int a1 = la[e + 1], b1 = lb[e + 1];   // N_LABEL even
    float r0 = g_pA[a0] + g_pB[b0] + fb;
    float r1 = g_pA[a1] + g_pB[b1] + fb;
    *(float2*)(out + e) = make_float2(r0, r1);
}

// ---------------------------------------------------------------------------
extern "C" void kernel_launch(void* const* d_in, const int* in_sizes, int n_in,
                              void* d_out, int out_size) {
    const int*   x     = (const int*)  d_in[0];
    const int*   ei    = (const int*)  d_in[1];
    const int*   eli   = (const int*)  d_in[2];
    const float* embed = (const float*)d_in[3];
    const float* W1    = (const float*)d_in[4];
    const float* b1    = (const float*)d_in[5];
    const float* W2    = (const float*)d_in[6];
    const float* b2    = (const float*)d_in[7];
    const float* fc_w  = (const float*)d_in[8];
    const float* fc_b  = (const float*)d_in[9];
    float*       out   = (float*)d_out;

    const int4* e_src4 = (const int4*)ei;
    const int4* e_dst4 = (const int4*)(ei + N_EDGES);
    const int*  l_a    = eli;
    const int*  l_b    = eli + N_LABEL;

    const int TB = 256;
    int gN  = (N_NODES + TB - 1) / TB;
    int gE8 = (N_EDGES / 8 + TB - 1) / TB;
    int gL2 = (N_LABEL / 2 + TB - 1) / TB;
    int gG  = N_NODES / 64;              // exact: 15625 blocks, 4 thr/node

    static cudaStream_t s2 = nullptr;
    static cudaEvent_t  e1 = nullptr, e2 = nullptr;
    static void* degPtr = nullptr;
    if (!e1) {
        if (cudaStreamCreateWithFlags(&s2, cudaStreamNonBlocking) != cudaSuccess) s2 = nullptr;
        cudaEventCreateWithFlags(&e1, cudaEventDisableTiming);
        cudaEventCreateWithFlags(&e2, cudaEventDisableTiming);
        cudaGetSymbolAddress(&degPtr, g_deg);
    }

    cudaMemsetAsync(degPtr, 0, N_NODES * sizeof(int), 0);
    k_count<<<gE8, TB>>>(e_dst4);

    if (s2) {
        cudaEventRecord(e1, 0);
        cudaStreamWaitEvent(s2, e1, 0);
        k_dinv<<<gN, TB, 0, s2>>>();
        k_mm1 <<<gN, TB, 0, s2>>>(x, embed, W1);
        cudaEventRecord(e2, s2);
        k_scan1<<<NB, 256>>>();
        k_scan2<<<1, 512>>>();
        k_scan3<<<gN, TB>>>();
        k_fill <<<gE8, TB>>>(e_src4, e_dst4);
        cudaStreamWaitEvent(0, e2, 0);
    } else {
        k_dinv <<<gN, TB>>>();
        k_scan1<<<NB, 256>>>();
        k_scan2<<<1, 512>>>();
        k_scan3<<<gN, TB>>>();
        k_fill <<<gE8, TB>>>(e_src4, e_dst4);
        k_mm1  <<<gN, TB>>>(x, embed, W1);
    }

    k_gather_mm2<<<gG, TB>>>(W2, b1);
    k_gather_z  <<<gG, TB>>>(b2, fc_w);
    k_predict   <<<gL2, TB>>>(l_a, l_b, fc_b, out);
}

// round 10
// speedup vs baseline: 1.0248x; 1.0134x over previous
#include <cuda_runtime.h>
#include <cuda_fp16.h>
#include <cstdint>

#define N_NODES 1000000
#define N_EDGES 5000000
#define N_LABEL 2000000
#define FDIM    16

#define SCAN_CHUNK 2048
#define NB ((N_NODES + SCAN_CHUNK - 1) / SCAN_CHUNK)   // 489

// Scratch (device globals — allocation is forbidden)
__device__ int      g_deg [N_NODES];
__device__ int      g_off [N_NODES + 1];
__device__ int      g_slot[N_EDGES];       // per-edge slot within its dst bucket
__device__ int      g_csr [N_EDGES];
__device__ int      g_bsum[NB];
__device__ float    g_dinv[N_NODES];
__device__ unsigned g_msg1[N_NODES * 8];   // layer-1 messages, half2-packed
__device__ unsigned g_msg2[N_NODES * 8];   // layer-2 messages, half2-packed
__device__ float    g_pA  [N_NODES];       // dot(z_i, fc_w[0:16])
__device__ float    g_pB  [N_NODES];       // dot(z_i, fc_w[16:32])

// ---------------------------------------------------------------------------
// E % 4 == 0: int4-vectorized degree count. The atomic's RETURN VALUE is the
// edge's slot within its dst bucket — recorded so k_fill needs no atomics.
__global__ void k_count(const int4* __restrict__ dst4) {
    int e = blockIdx.x * blockDim.x + threadIdx.x;
    if (e < N_EDGES / 4) {
        int4 d = dst4[e];
        int4 sl;
        sl.x = atomicAdd(&g_deg[d.x], 1);
        sl.y = atomicAdd(&g_deg[d.y], 1);
        sl.z = atomicAdd(&g_deg[d.z], 1);
        sl.w = atomicAdd(&g_deg[d.w], 1);
        ((int4*)g_slot)[e] = sl;
    }
}

// dinv only needs deg — runs on the side stream, unblocks mm1 early.
__global__ void k_dinv() {
    int i = blockIdx.x * blockDim.x + threadIdx.x;
    if (i < N_NODES) g_dinv[i] = rsqrtf((float)(g_deg[i] + 1));  // +1 self loop
}

// ---------------------------------------------------------------------------
// 3-phase exclusive scan of g_deg into g_off.
__global__ void k_scan1() {
    __shared__ int s[256];
    int b = blockIdx.x, t = threadIdx.x;
    int base = b * SCAN_CHUNK + t * 8;
    int v[8], sum = 0;
    #pragma unroll
    for (int q = 0; q < 8; q++) {
        int idx = base + q;
        int d = (idx < N_NODES) ? g_deg[idx] : 0;
        v[q] = sum; sum += d;
    }
    s[t] = sum; __syncthreads();
    for (int o = 1; o < 256; o <<= 1) {
        int x = (t >= o) ? s[t - o] : 0;
        __syncthreads();
        s[t] += x;
        __syncthreads();
    }
    int excl = (t > 0) ? s[t - 1] : 0;
    #pragma unroll
    for (int q = 0; q < 8; q++) {
        int idx = base + q;
        if (idx < N_NODES) g_off[idx] = v[q] + excl;
    }
    if (t == 255) g_bsum[b] = s[255];
}

__global__ void k_scan2() {
    __shared__ int s[512];
    int t = threadIdx.x;
    s[t] = (t < NB) ? g_bsum[t] : 0;
    __syncthreads();
    for (int o = 1; o < 512; o <<= 1) {
        int x = (t >= o) ? s[t - o] : 0;
        __syncthreads();
        s[t] += x;
        __syncthreads();
    }
    if (t < NB) g_bsum[t] = (t > 0) ? s[t - 1] : 0;   // exclusive
}

__global__ void k_scan3() {
    int i = blockIdx.x * blockDim.x + threadIdx.x;
    if (i < N_NODES) g_off[i] += g_bsum[i >> 11];
    if (i == 0) g_off[N_NODES] = N_EDGES;
}

// Atomic-free int4-vectorized CSR fill: pos = off[dst] + slot
__global__ void k_fill(const int4* __restrict__ src4, const int4* __restrict__ dst4) {
    int e = blockIdx.x * blockDim.x + threadIdx.x;
    if (e >= N_EDGES / 4) return;
    int4 s  = src4[e];
    int4 d  = dst4[e];
    int4 sl = ((const int4*)g_slot)[e];
    g_csr[g_off[d.x] + sl.x] = s.x;
    g_csr[g_off[d.y] + sl.y] = s.y;
    g_csr[g_off[d.z] + sl.z] = s.z;
    g_csr[g_off[d.w] + sl.w] = s.w;
}

// ---------------------------------------------------------------------------
// K-mm1: msg1[i] = (embed[x[i]] @ W1) * dinv[i]  (half2-packed, 32 B/node)
__global__ void k_mm1(const int* __restrict__ x,
                      const float* __restrict__ embed,
                      const float* __restrict__ W1) {
    __shared__ float Ws[FDIM][FDIM];
    if (threadIdx.x < 256) {
        int k = threadIdx.x >> 4, j = threadIdx.x & 15;
        Ws[k][j] = W1[threadIdx.x];
    }
    __syncthreads();

    int i = blockIdx.x * blockDim.x + threadIdx.x;
    if (i >= N_NODES) return;

    const float4* rp = (const float4*)(embed + (size_t)x[i] * FDIM);
    float4 r0 = rp[0], r1 = rp[1], r2 = rp[2], r3 = rp[3];
    float row[FDIM] = {r0.x,r0.y,r0.z,r0.w, r1.x,r1.y,r1.z,r1.w,
                       r2.x,r2.y,r2.z,r2.w, r3.x,r3.y,r3.z,r3.w};
    float dv = g_dinv[i];
    float out[FDIM];
    #pragma unroll
    for (int j = 0; j < FDIM; j++) {
        float acc = 0.f;
        #pragma unroll
        for (int k = 0; k < FDIM; k++) acc = fmaf(row[k], Ws[k][j], acc);
        out[j] = acc * dv;
    }
    __half2 h[8];
    #pragma unroll
    for (int q = 0; q < 8; q++) h[q] = __floats2half2_rn(out[2*q], out[2*q+1]);
    uint4* mp = (uint4*)(g_msg1 + (size_t)i * 8);
    mp[0] = make_uint4(*(unsigned*)&h[0], *(unsigned*)&h[1], *(unsigned*)&h[2], *(unsigned*)&h[3]);
    mp[1] = make_uint4(*(unsigned*)&h[4], *(unsigned*)&h[5], *(unsigned*)&h[6], *(unsigned*)&h[7]);
}

// ---------------------------------------------------------------------------
__device__ __forceinline__ void acc_h4(float4& a, uint2 m) {
    float2 f0 = __half22float2(*(__half2*)&m.x);
    float2 f1 = __half22float2(*(__half2*)&m.y);
    a.x += f0.x; a.y += f0.y; a.z += f1.x; a.w += f1.y;
}

// Gather core (R6 form): 4 threads/node, uint2 loads, batches of 4 with
// clamped indices + predicated accumulate — no serial remainder chain.
__device__ __forceinline__ float4 gather_acc(const uint2* __restrict__ M,
                                             int node, int t, int o0, int o1) {
    float4 acc = make_float4(0.f, 0.f, 0.f, 0.f);
    acc_h4(acc, M[(size_t)node * 4 + t]);          // self message

    int last = o1 - 1;
    for (int j = o0; j < o1; j += 4) {
        int j1 = min(j + 1, last), j2 = min(j + 2, last), j3 = min(j + 3, last);
        int s0 = g_csr[j],  s1 = g_csr[j1];
        int s2 = g_csr[j2], s3 = g_csr[j3];
        uint2 m0 = M[(size_t)s0 * 4 + t];
        uint2 m1 = M[(size_t)s1 * 4 + t];
        uint2 m2 = M[(size_t)s2 * 4 + t];
        uint2 m3 = M[(size_t)s3 * 4 + t];
        acc_h4(acc, m0);
        if (j + 1 < o1) acc_h4(acc, m1);
        if (j + 2 < o1) acc_h4(acc, m2);
        if (j + 3 < o1) acc_h4(acc, m3);
    }
    return acc;
}

// K-gather1 fused with layer-2 matmul. Grid exact: 1e6/64 blocks — full warps.
__global__ void k_gather_mm2(const float* __restrict__ W2,
                             const float* __restrict__ b1) {
    __shared__ float Ws[FDIM][FDIM];
    __shared__ float bs[FDIM];
    if (threadIdx.x < 256) {
        int k = threadIdx.x >> 4, j = threadIdx.x & 15;
        Ws[k][j] = W2[threadIdx.x];
        if (threadIdx.x < FDIM) bs[threadIdx.x] = b1[threadIdx.x];
    }
    __syncthreads();

    int node  = blockIdx.x * 64 + (threadIdx.x >> 2);
    int t     = threadIdx.x & 3;
    int gbase = (threadIdx.x & 31) & ~3;

    float4 acc = gather_acc((const uint2*)g_msg1, node, t,
                            g_off[node], g_off[node + 1]);

    float dv = g_dinv[node];
    float h[4];
    h[0] = fmaxf(fmaf(dv, acc.x, bs[4*t + 0]), 0.f);
    h[1] = fmaxf(fmaf(dv, acc.y, bs[4*t + 1]), 0.f);
    h[2] = fmaxf(fmaf(dv, acc.z, bs[4*t + 2]), 0.f);
    h[3] = fmaxf(fmaf(dv, acc.w, bs[4*t + 3]), 0.f);

    float o[4] = {0.f, 0.f, 0.f, 0.f};
    #pragma unroll
    for (int k = 0; k < FDIM; k++) {
        float hk = __shfl_sync(0xFFFFFFFFu, h[k & 3], gbase + (k >> 2));
        o[0] = fmaf(hk, Ws[k][4*t + 0], o[0]);
        o[1] = fmaf(hk, Ws[k][4*t + 1], o[1]);
        o[2] = fmaf(hk, Ws[k][4*t + 2], o[2]);
        o[3] = fmaf(hk, Ws[k][4*t + 3], o[3]);
    }
    __half2 p0 = __floats2half2_rn(o[0] * dv, o[1] * dv);
    __half2 p1 = __floats2half2_rn(o[2] * dv, o[3] * dv);
    ((uint2*)g_msg2)[(size_t)node * 4 + t] =
        make_uint2(*(unsigned*)&p0, *(unsigned*)&p1);
}

// K-gather2 fused with final FC partials:
//   z = dinv*(msg2[i] + Σ msg2[s]) + b2
//   pA[i] = dot(z, fc_w[0:16]);  pB[i] = dot(z, fc_w[16:32])
__global__ void k_gather_z(const float* __restrict__ b2,
                           const float* __restrict__ fc_w) {
    __shared__ float bs[FDIM];
    __shared__ float fw[32];
    if (threadIdx.x < FDIM) bs[threadIdx.x] = b2[threadIdx.x];
    if (threadIdx.x < 32)   fw[threadIdx.x] = fc_w[threadIdx.x];
    __syncthreads();

    int node = blockIdx.x * 64 + (threadIdx.x >> 2);
    int t    = threadIdx.x & 3;

    float4 acc = gather_acc((const uint2*)g_msg2, node, t,
                            g_off[node], g_off[node + 1]);

    float dv = g_dinv[node];
    float z0 = fmaf(dv, acc.x, bs[4*t + 0]);
    float z1 = fmaf(dv, acc.y, bs[4*t + 1]);
    float z2 = fmaf(dv, acc.z, bs[4*t + 2]);
    float z3 = fmaf(dv, acc.w, bs[4*t + 3]);

    float pa = z0 * fw[4*t] + z1 * fw[4*t+1] + z2 * fw[4*t+2] + z3 * fw[4*t+3];
    float pb = z0 * fw[16+4*t] + z1 * fw[16+4*t+1]
             + z2 * fw[16+4*t+2] + z3 * fw[16+4*t+3];

    pa += __shfl_xor_sync(0xFFFFFFFFu, pa, 1);
    pa += __shfl_xor_sync(0xFFFFFFFFu, pa, 2);
    pb += __shfl_xor_sync(0xFFFFFFFFu, pb, 1);
    pb += __shfl_xor_sync(0xFFFFFFFFu, pb, 2);

    if (t == 0) {
        g_pA[node] = pa;
        g_pB[node] = pb;
    }
}

// ---------------------------------------------------------------------------
// K-predict: out[e] = pA[la[e]] + pB[lb[e]] + fc_b
__global__ void k_predict(const int* __restrict__ la,
                          const int* __restrict__ lb,
                          const float* __restrict__ fc_b,
                          float* __restrict__ out) {
    int e = blockIdx.x * blockDim.x + threadIdx.x;
    if (e >= N_LABEL) return;
    float fb = __ldg(fc_b);
    out[e] = g_pA[la[e]] + g_pB[lb[e]] + fb;
}

// ---------------------------------------------------------------------------
extern "C" void kernel_launch(void* const* d_in, const int* in_sizes, int n_in,
                              void* d_out, int out_size) {
    const int*   x     = (const int*)  d_in[0];
    const int*   ei    = (const int*)  d_in[1];
    const int*   eli   = (const int*)  d_in[2];
    const float* embed = (const float*)d_in[3];
    const float* W1    = (const float*)d_in[4];
    const float* b1    = (const float*)d_in[5];
    const float* W2    = (const float*)d_in[6];
    const float* b2    = (const float*)d_in[7];
    const float* fc_w  = (const float*)d_in[8];
    const float* fc_b  = (const float*)d_in[9];
    float*       out   = (float*)d_out;

    const int4* e_src4 = (const int4*)ei;
    const int4* e_dst4 = (const int4*)(ei + N_EDGES);
    const int*  l_a    = eli;
    const int*  l_b    = eli + N_LABEL;

    const int TB = 256;
    int gN  = (N_NODES + TB - 1) / TB;
    int gE4 = (N_EDGES / 4 + TB - 1) / TB;
    int gL  = (N_LABEL + TB - 1) / TB;
    int gG  = N_NODES / 64;              // exact: 15625 blocks, 4 thr/node

    static cudaStream_t s2 = nullptr;
    static cudaEvent_t  e1 = nullptr, e2 = nullptr;
    static void* degPtr = nullptr;
    if (!e1) {
        if (cudaStreamCreateWithFlags(&s2, cudaStreamNonBlocking) != cudaSuccess) s2 = nullptr;
        cudaEventCreateWithFlags(&e1, cudaEventDisableTiming);
        cudaEventCreateWithFlags(&e2, cudaEventDisableTiming);
        cudaGetSymbolAddress(&degPtr, g_deg);
    }

    cudaMemsetAsync(degPtr, 0, N_NODES * sizeof(int), 0);
    k_count<<<gE4, TB>>>(e_dst4);

    if (s2) {
        cudaEventRecord(e1, 0);
        cudaStreamWaitEvent(s2, e1, 0);
        k_dinv<<<gN, TB, 0, s2>>>();
        k_mm1 <<<gN, TB, 0, s2>>>(x, embed, W1);
        cudaEventRecord(e2, s2);
        k_scan1<<<NB, 256>>>();
        k_scan2<<<1, 512>>>();
        k_scan3<<<gN, TB>>>();
        k_fill <<<gE4, TB>>>(e_src4, e_dst4);
        cudaStreamWaitEvent(0, e2, 0);
    } else {
        k_dinv <<<gN, TB>>>();
        k_scan1<<<NB, 256>>>();
        k_scan2<<<1, 512>>>();
        k_scan3<<<gN, TB>>>();
        k_fill <<<gE4, TB>>>(e_src4, e_dst4);
        k_mm1  <<<gN, TB>>>(x, embed, W1);
    }

    k_gather_mm2<<<gG, TB>>>(W2, b1);
    k_gather_z  <<<gG, TB>>>(b2, fc_w);
    k_predict   <<<gL, TB>>>(l_a, l_b, fc_b, out);
}